// round 5
// baseline (speedup 1.0000x reference)
#include <cuda_runtime.h>
#include <math.h>

#define NB    256
#define NRES  1024
#define NATOM 37
#define STRN  (NATOM*3)   // 111 floats per residue
#define CA    1

__device__ float g_rmsd[NB];

// One block per batch: reduce 18 moments over CA atoms, then analytic
// 3x3 Kabsch trace -> rmsd[b].
__global__ __launch_bounds__(256) void rmsd_batch_kernel(
    const float* __restrict__ pred,
    const float* __restrict__ tru,
    const float* __restrict__ mask)
{
    const int b = blockIdx.x;
    const int t = threadIdx.x;

    const float* pb = pred + (size_t)b * NRES * STRN + CA * 3;
    const float* tb = tru  + (size_t)b * NRES * STRN + CA * 3;
    const float* mb = mask + (size_t)b * NRES * NATOM + CA;

    // 0: sum m
    // 1..3:  sum m*p ; 4..6: sum m*t
    // 7..15: sum m*p_i*t_j (row-major i,j)
    // 16: sum m*|p|^2 ; 17: sum m*|t|^2
    float acc[18];
#pragma unroll
    for (int i = 0; i < 18; i++) acc[i] = 0.f;

#pragma unroll 4
    for (int n = t; n < NRES; n += 256) {
        const float* pp = pb + (size_t)n * STRN;
        const float* tt = tb + (size_t)n * STRN;
        float m  = __ldg(mb + (size_t)n * NATOM);
        float px = __ldg(pp + 0), py = __ldg(pp + 1), pz = __ldg(pp + 2);
        float tx = __ldg(tt + 0), ty = __ldg(tt + 1), tz = __ldg(tt + 2);

        acc[0]  += m;
        acc[1]  += m * px;  acc[2]  += m * py;  acc[3]  += m * pz;
        acc[4]  += m * tx;  acc[5]  += m * ty;  acc[6]  += m * tz;
        acc[7]  += m * px * tx;  acc[8]  += m * px * ty;  acc[9]  += m * px * tz;
        acc[10] += m * py * tx;  acc[11] += m * py * ty;  acc[12] += m * py * tz;
        acc[13] += m * pz * tx;  acc[14] += m * pz * ty;  acc[15] += m * pz * tz;
        acc[16] += m * (px * px + py * py + pz * pz);
        acc[17] += m * (tx * tx + ty * ty + tz * tz);
    }

    // intra-warp tree reduce
#pragma unroll
    for (int i = 0; i < 18; i++) {
#pragma unroll
        for (int o = 16; o > 0; o >>= 1)
            acc[i] += __shfl_down_sync(0xffffffffu, acc[i], o);
    }

    __shared__ float sh[8][18];
    const int w = t >> 5, lane = t & 31;
    if (lane == 0) {
#pragma unroll
        for (int i = 0; i < 18; i++) sh[w][i] = acc[i];
    }
    __syncthreads();

    if (t == 0) {
        double s[18];
#pragma unroll
        for (int i = 0; i < 18; i++) {
            double v = 0.0;
#pragma unroll
            for (int k = 0; k < 8; k++) v += (double)sh[k][i];
            s[i] = v;
        }

        const double msum = s[0] + 1e-8;
        double pc[3] = { s[1] / msum, s[2] / msum, s[3] / msum };
        double tc[3] = { s[4] / msum, s[5] / msum, s[6] / msum };

        // H_ij = sum m (p_i - pc_i)(t_j - tc_j)
        double H[3][3];
#pragma unroll
        for (int i = 0; i < 3; i++)
#pragma unroll
            for (int j = 0; j < 3; j++)
                H[i][j] = s[7 + i * 3 + j] - pc[i] * s[4 + j]
                        - tc[j] * s[1 + i] + pc[i] * tc[j] * s[0];

        const double Sp = s[16] - 2.0 * (pc[0]*s[1] + pc[1]*s[2] + pc[2]*s[3])
                        + (pc[0]*pc[0] + pc[1]*pc[1] + pc[2]*pc[2]) * s[0];
        const double St = s[17] - 2.0 * (tc[0]*s[4] + tc[1]*s[5] + tc[2]*s[6])
                        + (tc[0]*tc[0] + tc[1]*tc[1] + tc[2]*tc[2]) * s[0];

        const double detH =
              H[0][0] * (H[1][1]*H[2][2] - H[1][2]*H[2][1])
            - H[0][1] * (H[1][0]*H[2][2] - H[1][2]*H[2][0])
            + H[0][2] * (H[1][0]*H[2][1] - H[1][1]*H[2][0]);

        // A = H^T H (symmetric PSD); closed-form eigenvalues (Smith).
        double A[3][3];
#pragma unroll
        for (int i = 0; i < 3; i++)
#pragma unroll
            for (int j = 0; j < 3; j++)
                A[i][j] = H[0][i]*H[0][j] + H[1][i]*H[1][j] + H[2][i]*H[2][j];

        const double q  = (A[0][0] + A[1][1] + A[2][2]) / 3.0;
        const double p1 = A[0][1]*A[0][1] + A[0][2]*A[0][2] + A[1][2]*A[1][2];
        const double p2 = (A[0][0]-q)*(A[0][0]-q) + (A[1][1]-q)*(A[1][1]-q)
                        + (A[2][2]-q)*(A[2][2]-q) + 2.0 * p1;

        double e1, e2, e3;
        if (p2 <= 1e-300) {
            e1 = e2 = e3 = q;
        } else {
            const double p = sqrt(p2 / 6.0);
            double Bm[3][3];
#pragma unroll
            for (int i = 0; i < 3; i++)
#pragma unroll
                for (int j = 0; j < 3; j++)
                    Bm[i][j] = (A[i][j] - (i == j ? q : 0.0)) / p;
            double detB =
                  Bm[0][0]*(Bm[1][1]*Bm[2][2] - Bm[1][2]*Bm[2][1])
                - Bm[0][1]*(Bm[1][0]*Bm[2][2] - Bm[1][2]*Bm[2][0])
                + Bm[0][2]*(Bm[1][0]*Bm[2][1] - Bm[1][1]*Bm[2][0]);
            double r = detB * 0.5;
            r = fmin(1.0, fmax(-1.0, r));
            const double phi = acos(r) / 3.0;
            e1 = q + 2.0 * p * cos(phi);
            e3 = q + 2.0 * p * cos(phi + 2.0943951023931953);  // +2pi/3
            e2 = 3.0 * q - e1 - e3;
        }

        const double s1 = sqrt(fmax(e1, 0.0));
        const double s2 = sqrt(fmax(e2, 0.0));
        const double s3 = sqrt(fmax(e3, 0.0));
        const double trRH = s1 + s2 + (detH < 0.0 ? -s3 : s3);

        const double r2 = fmax((Sp + St - 2.0 * trRH) / msum, 0.0);
        g_rmsd[b] = (float)sqrt(r2);
    }
}

__global__ __launch_bounds__(256) void rmsd_mean_kernel(float* __restrict__ out)
{
    const int t = threadIdx.x;
    float v = g_rmsd[t];
#pragma unroll
    for (int o = 16; o > 0; o >>= 1)
        v += __shfl_down_sync(0xffffffffu, v, o);

    __shared__ float sh[8];
    if ((t & 31) == 0) sh[t >> 5] = v;
    __syncthreads();
    if (t == 0) {
        float s = 0.f;
#pragma unroll
        for (int k = 0; k < 8; k++) s += sh[k];
        out[0] = s / (float)NB;
    }
}

extern "C" void kernel_launch(void* const* d_in, const int* in_sizes, int n_in,
                              void* d_out, int out_size)
{
    const float* pred = (const float*)d_in[0];
    const float* tru  = (const float*)d_in[1];
    const float* mask = (const float*)d_in[2];
    float* out = (float*)d_out;

    rmsd_batch_kernel<<<NB, 256>>>(pred, tru, mask);
    rmsd_mean_kernel<<<1, 256>>>(out);
}

// round 6
// speedup vs baseline: 2.3966x; 2.3966x over previous
#include <cuda_runtime.h>
#include <math.h>

#define NB    256
#define NRES  1024
#define NATOM 37
#define STRN  (NATOM*3)   // 111 floats per residue
#define CA    1

__device__ float    g_rmsd[NB];
__device__ unsigned g_done = 0;   // wraps back to 0 via atomicInc -> deterministic across replays

// One block per batch: reduce 18 moments over CA atoms (fp32), analytic 3x3
// Kabsch trace in fp32, then last-finished block computes the mean.
__global__ __launch_bounds__(256) void rmsd_fused_kernel(
    const float* __restrict__ pred,
    const float* __restrict__ tru,
    const float* __restrict__ mask,
    float* __restrict__ out)
{
    const int b = blockIdx.x;
    const int t = threadIdx.x;

    const float* pb = pred + (size_t)b * NRES * STRN + CA * 3;
    const float* tb = tru  + (size_t)b * NRES * STRN + CA * 3;
    const float* mb = mask + (size_t)b * NRES * NATOM + CA;

    // 0: sum m
    // 1..3:  sum m*p ; 4..6: sum m*t
    // 7..15: sum m*p_i*t_j (row-major i,j)
    // 16: sum m*|p|^2 ; 17: sum m*|t|^2
    float acc[18];
#pragma unroll
    for (int i = 0; i < 18; i++) acc[i] = 0.f;

#pragma unroll
    for (int it = 0; it < NRES / 256; it++) {
        const int n = t + it * 256;
        const float* pp = pb + (size_t)n * STRN;
        const float* tt = tb + (size_t)n * STRN;
        float m  = __ldg(mb + (size_t)n * NATOM);
        float px = __ldg(pp + 0), py = __ldg(pp + 1), pz = __ldg(pp + 2);
        float tx = __ldg(tt + 0), ty = __ldg(tt + 1), tz = __ldg(tt + 2);

        acc[0]  += m;
        acc[1]  += m * px;  acc[2]  += m * py;  acc[3]  += m * pz;
        acc[4]  += m * tx;  acc[5]  += m * ty;  acc[6]  += m * tz;
        acc[7]  += m * px * tx;  acc[8]  += m * px * ty;  acc[9]  += m * px * tz;
        acc[10] += m * py * tx;  acc[11] += m * py * ty;  acc[12] += m * py * tz;
        acc[13] += m * pz * tx;  acc[14] += m * pz * ty;  acc[15] += m * pz * tz;
        acc[16] += m * (px * px + py * py + pz * pz);
        acc[17] += m * (tx * tx + ty * ty + tz * tz);
    }

    // intra-warp tree reduce
#pragma unroll
    for (int i = 0; i < 18; i++) {
#pragma unroll
        for (int o = 16; o > 0; o >>= 1)
            acc[i] += __shfl_down_sync(0xffffffffu, acc[i], o);
    }

    __shared__ float sh[8][18];
    __shared__ int   is_last;
    const int w = t >> 5, lane = t & 31;
    if (lane == 0) {
#pragma unroll
        for (int i = 0; i < 18; i++) sh[w][i] = acc[i];
    }
    __syncthreads();

    if (t == 0) {
        float s[18];
#pragma unroll
        for (int i = 0; i < 18; i++) {
            float v = 0.f;
#pragma unroll
            for (int k = 0; k < 8; k++) v += sh[k][i];
            s[i] = v;
        }

        const float msum = s[0] + 1e-8f;
        const float inv  = 1.f / msum;
        float pc[3] = { s[1] * inv, s[2] * inv, s[3] * inv };
        float tc[3] = { s[4] * inv, s[5] * inv, s[6] * inv };

        // H_ij = sum m (p_i - pc_i)(t_j - tc_j)
        float H[3][3];
#pragma unroll
        for (int i = 0; i < 3; i++)
#pragma unroll
            for (int j = 0; j < 3; j++)
                H[i][j] = s[7 + i * 3 + j] - pc[i] * s[4 + j]
                        - tc[j] * s[1 + i] + pc[i] * tc[j] * s[0];

        const float Sp = s[16] - 2.f * (pc[0]*s[1] + pc[1]*s[2] + pc[2]*s[3])
                       + (pc[0]*pc[0] + pc[1]*pc[1] + pc[2]*pc[2]) * s[0];
        const float St = s[17] - 2.f * (tc[0]*s[4] + tc[1]*s[5] + tc[2]*s[6])
                       + (tc[0]*tc[0] + tc[1]*tc[1] + tc[2]*tc[2]) * s[0];

        const float detH =
              H[0][0] * (H[1][1]*H[2][2] - H[1][2]*H[2][1])
            - H[0][1] * (H[1][0]*H[2][2] - H[1][2]*H[2][0])
            + H[0][2] * (H[1][0]*H[2][1] - H[1][1]*H[2][0]);

        // A = H^T H (symmetric PSD); closed-form eigenvalues (Smith).
        float A[3][3];
#pragma unroll
        for (int i = 0; i < 3; i++)
#pragma unroll
            for (int j = 0; j < 3; j++)
                A[i][j] = H[0][i]*H[0][j] + H[1][i]*H[1][j] + H[2][i]*H[2][j];

        const float q  = (A[0][0] + A[1][1] + A[2][2]) * (1.f / 3.f);
        const float p1 = A[0][1]*A[0][1] + A[0][2]*A[0][2] + A[1][2]*A[1][2];
        const float p2 = (A[0][0]-q)*(A[0][0]-q) + (A[1][1]-q)*(A[1][1]-q)
                       + (A[2][2]-q)*(A[2][2]-q) + 2.f * p1;

        float e1, e2, e3;
        if (p2 <= 1e-30f) {
            e1 = e2 = e3 = q;
        } else {
            const float p    = sqrtf(p2 * (1.f / 6.f));
            const float invp = 1.f / p;
            float Bm[3][3];
#pragma unroll
            for (int i = 0; i < 3; i++)
#pragma unroll
                for (int j = 0; j < 3; j++)
                    Bm[i][j] = (A[i][j] - (i == j ? q : 0.f)) * invp;
            float detB =
                  Bm[0][0]*(Bm[1][1]*Bm[2][2] - Bm[1][2]*Bm[2][1])
                - Bm[0][1]*(Bm[1][0]*Bm[2][2] - Bm[1][2]*Bm[2][0])
                + Bm[0][2]*(Bm[1][0]*Bm[2][1] - Bm[1][1]*Bm[2][0]);
            float r = detB * 0.5f;
            r = fminf(1.f, fmaxf(-1.f, r));
            const float phi = acosf(r) * (1.f / 3.f);
            e1 = q + 2.f * p * cosf(phi);
            e3 = q + 2.f * p * cosf(phi + 2.0943951023931953f);  // +2pi/3
            e2 = 3.f * q - e1 - e3;
        }

        const float s1 = sqrtf(fmaxf(e1, 0.f));
        const float s2 = sqrtf(fmaxf(e2, 0.f));
        const float s3 = sqrtf(fmaxf(e3, 0.f));
        const float trRH = s1 + s2 + (detH < 0.f ? -s3 : s3);

        const float r2 = fmaxf((Sp + St - 2.f * trRH) * inv, 0.f);
        g_rmsd[b] = sqrtf(r2);

        // publish + claim ticket; counter self-resets to 0 on the last arrival
        __threadfence();
        unsigned old = atomicInc(&g_done, NB - 1);
        is_last = (old == NB - 1);
    }
    __syncthreads();

    // last-arriving block computes the mean over all batches
    if (is_last) {
        float v = __ldcg(&g_rmsd[t]);   // L2 read; bypass (cold) L1
#pragma unroll
        for (int o = 16; o > 0; o >>= 1)
            v += __shfl_down_sync(0xffffffffu, v, o);
        if (lane == 0) sh[0][w] = v;    // reuse smem
        __syncthreads();
        if (t == 0) {
            float sum = 0.f;
#pragma unroll
            for (int k = 0; k < 8; k++) sum += sh[0][k];
            out[0] = sum * (1.f / (float)NB);
        }
    }
}

extern "C" void kernel_launch(void* const* d_in, const int* in_sizes, int n_in,
                              void* d_out, int out_size)
{
    const float* pred = (const float*)d_in[0];
    const float* tru  = (const float*)d_in[1];
    const float* mask = (const float*)d_in[2];
    float* out = (float*)d_out;

    rmsd_fused_kernel<<<NB, 256>>>(pred, tru, mask, out);
}

// round 11
// speedup vs baseline: 2.4017x; 1.0022x over previous
#include <cuda_runtime.h>
#include <math.h>

#define NB    256
#define NRES  1024
#define NATOM 37
#define STRN  (NATOM*3)   // 111 floats per residue
#define CA    1

__device__ float    g_rmsd[NB];
__device__ unsigned g_done = 0;   // wraps back to 0 via atomicInc -> deterministic across replays

// One block per batch: reduce 18 moments over CA atoms (fp32), analytic 3x3
// Kabsch trace in fp32, then last-finished block computes the mean.
__global__ __launch_bounds__(256) void rmsd_fused_kernel(
    const float* __restrict__ pred,
    const float* __restrict__ tru,
    const float* __restrict__ mask,
    float* __restrict__ out)
{
    const int b = blockIdx.x;
    const int t = threadIdx.x;

    const float* pb = pred + (size_t)b * NRES * STRN + CA * 3;
    const float* tb = tru  + (size_t)b * NRES * STRN + CA * 3;
    const float* mb = mask + (size_t)b * NRES * NATOM + CA;

    // 0: sum m
    // 1..3:  sum m*p ; 4..6: sum m*t
    // 7..15: sum m*p_i*t_j (row-major i,j)
    // 16: sum m*|p|^2 ; 17: sum m*|t|^2
    float acc[18];
#pragma unroll
    for (int i = 0; i < 18; i++) acc[i] = 0.f;

#pragma unroll
    for (int it = 0; it < NRES / 256; it++) {
        const int n = t + it * 256;
        const float* pp = pb + (size_t)n * STRN;
        const float* tt = tb + (size_t)n * STRN;
        float m  = __ldg(mb + (size_t)n * NATOM);
        float px = __ldg(pp + 0), py = __ldg(pp + 1), pz = __ldg(pp + 2);
        float tx = __ldg(tt + 0), ty = __ldg(tt + 1), tz = __ldg(tt + 2);

        acc[0]  += m;
        acc[1]  += m * px;  acc[2]  += m * py;  acc[3]  += m * pz;
        acc[4]  += m * tx;  acc[5]  += m * ty;  acc[6]  += m * tz;
        acc[7]  += m * px * tx;  acc[8]  += m * px * ty;  acc[9]  += m * px * tz;
        acc[10] += m * py * tx;  acc[11] += m * py * ty;  acc[12] += m * py * tz;
        acc[13] += m * pz * tx;  acc[14] += m * pz * ty;  acc[15] += m * pz * tz;
        acc[16] += m * (px * px + py * py + pz * pz);
        acc[17] += m * (tx * tx + ty * ty + tz * tz);
    }

    // intra-warp tree reduce
#pragma unroll
    for (int i = 0; i < 18; i++) {
#pragma unroll
        for (int o = 16; o > 0; o >>= 1)
            acc[i] += __shfl_down_sync(0xffffffffu, acc[i], o);
    }

    __shared__ float sh[8][18];
    __shared__ int   is_last;
    const int w = t >> 5, lane = t & 31;
    if (lane == 0) {
#pragma unroll
        for (int i = 0; i < 18; i++) sh[w][i] = acc[i];
    }
    __syncthreads();

    if (t == 0) {
        float s[18];
#pragma unroll
        for (int i = 0; i < 18; i++) {
            float v = 0.f;
#pragma unroll
            for (int k = 0; k < 8; k++) v += sh[k][i];
            s[i] = v;
        }

        const float msum = s[0] + 1e-8f;
        const float inv  = 1.f / msum;
        float pc[3] = { s[1] * inv, s[2] * inv, s[3] * inv };
        float tc[3] = { s[4] * inv, s[5] * inv, s[6] * inv };

        // H_ij = sum m (p_i - pc_i)(t_j - tc_j)
        float H[3][3];
#pragma unroll
        for (int i = 0; i < 3; i++)
#pragma unroll
            for (int j = 0; j < 3; j++)
                H[i][j] = s[7 + i * 3 + j] - pc[i] * s[4 + j]
                        - tc[j] * s[1 + i] + pc[i] * tc[j] * s[0];

        const float Sp = s[16] - 2.f * (pc[0]*s[1] + pc[1]*s[2] + pc[2]*s[3])
                       + (pc[0]*pc[0] + pc[1]*pc[1] + pc[2]*pc[2]) * s[0];
        const float St = s[17] - 2.f * (tc[0]*s[4] + tc[1]*s[5] + tc[2]*s[6])
                       + (tc[0]*tc[0] + tc[1]*tc[1] + tc[2]*tc[2]) * s[0];

        const float detH =
              H[0][0] * (H[1][1]*H[2][2] - H[1][2]*H[2][1])
            - H[0][1] * (H[1][0]*H[2][2] - H[1][2]*H[2][0])
            + H[0][2] * (H[1][0]*H[2][1] - H[1][1]*H[2][0]);

        // A = H^T H (symmetric PSD); closed-form eigenvalues (Smith).
        float A[3][3];
#pragma unroll
        for (int i = 0; i < 3; i++)
#pragma unroll
            for (int j = 0; j < 3; j++)
                A[i][j] = H[0][i]*H[0][j] + H[1][i]*H[1][j] + H[2][i]*H[2][j];

        const float q  = (A[0][0] + A[1][1] + A[2][2]) * (1.f / 3.f);
        const float p1 = A[0][1]*A[0][1] + A[0][2]*A[0][2] + A[1][2]*A[1][2];
        const float p2 = (A[0][0]-q)*(A[0][0]-q) + (A[1][1]-q)*(A[1][1]-q)
                       + (A[2][2]-q)*(A[2][2]-q) + 2.f * p1;

        float e1, e2, e3;
        if (p2 <= 1e-30f) {
            e1 = e2 = e3 = q;
        } else {
            const float p    = sqrtf(p2 * (1.f / 6.f));
            const float invp = 1.f / p;
            float Bm[3][3];
#pragma unroll
            for (int i = 0; i < 3; i++)
#pragma unroll
                for (int j = 0; j < 3; j++)
                    Bm[i][j] = (A[i][j] - (i == j ? q : 0.f)) * invp;
            float detB =
                  Bm[0][0]*(Bm[1][1]*Bm[2][2] - Bm[1][2]*Bm[2][1])
                - Bm[0][1]*(Bm[1][0]*Bm[2][2] - Bm[1][2]*Bm[2][0])
                + Bm[0][2]*(Bm[1][0]*Bm[2][1] - Bm[1][1]*Bm[2][0]);
            float r = detB * 0.5f;
            r = fminf(1.f, fmaxf(-1.f, r));
            const float phi = acosf(r) * (1.f / 3.f);
            e1 = q + 2.f * p * cosf(phi);
            e3 = q + 2.f * p * cosf(phi + 2.0943951023931953f);  // +2pi/3
            e2 = 3.f * q - e1 - e3;
        }

        const float s1 = sqrtf(fmaxf(e1, 0.f));
        const float s2 = sqrtf(fmaxf(e2, 0.f));
        const float s3 = sqrtf(fmaxf(e3, 0.f));
        const float trRH = s1 + s2 + (detH < 0.f ? -s3 : s3);

        const float r2 = fmaxf((Sp + St - 2.f * trRH) * inv, 0.f);
        g_rmsd[b] = sqrtf(r2);

        // publish + claim ticket; counter self-resets to 0 on the last arrival
        __threadfence();
        unsigned old = atomicInc(&g_done, NB - 1);
        is_last = (old == NB - 1);
    }
    __syncthreads();

    // last-arriving block computes the mean over all batches
    if (is_last) {
        float v = __ldcg(&g_rmsd[t]);   // L2 read; bypass (cold) L1
#pragma unroll
        for (int o = 16; o > 0; o >>= 1)
            v += __shfl_down_sync(0xffffffffu, v, o);
        if (lane == 0) sh[0][w] = v;    // reuse smem
        __syncthreads();
        if (t == 0) {
            float sum = 0.f;
#pragma unroll
            for (int k = 0; k < 8; k++) sum += sh[0][k];
            out[0] = sum * (1.f / (float)NB);
        }
    }
}

extern "C" void kernel_launch(void* const* d_in, const int* in_sizes, int n_in,
                              void* d_out, int out_size)
{
    const float* pred = (const float*)d_in[0];
    const float* tru  = (const float*)d_in[1];
    const float* mask = (const float*)d_in[2];
    float* out = (float*)d_out;

    rmsd_fused_kernel<<<NB, 256>>>(pred, tru, mask, out);
}